// round 15
// baseline (speedup 1.0000x reference)
#include <cuda_runtime.h>
#include <cuda_bf16.h>
#include <math.h>
#include <stdint.h>

#define BB   4
#define LL   2048
#define DM   1024
#define DI   2048
#define D2   4096      // 2*DI
#define DS   16
#define DR   64
#define NPROJ 96       // DR + 2*DS
#define MTOT (BB*LL)   // 8192
#define ASZ  (128*36)  // one GEMM tile stage (words)
#define NC   32        // scan chunks
#define CH   64        // steps per chunk
#define KSPL 4         // x_proj K splits
#define NPAD 128       // x_proj partial leading dim
#define CT   16        // conv timesteps per thread

// ---------------- scratch ----------------
__device__ __nv_bfloat16 g_hb[(size_t)MTOT * DM];
__device__ __nv_bfloat16 g_xzb[(size_t)MTOT * D2];
__device__ __nv_bfloat16 g_ub[(size_t)MTOT * DI];
__device__ float g_proj[(size_t)MTOT * NPROJ];
__device__ __nv_bfloat16 g_pdtb[(size_t)MTOT * DR];
__device__ float g_projp[(size_t)KSPL * MTOT * NPAD];
__device__ __nv_bfloat16 g_dtb[(size_t)MTOT * DI];
__device__ __nv_bfloat16 g_ygb[(size_t)MTOT * DI];
__device__ float g_state[(size_t)BB * NC * DI * DS];
__device__ float g_dtsum[(size_t)BB * NC * DI];
__device__ int   g_flag[BB * NC * 32];
__device__ __nv_bfloat16 g_Winb[(size_t)D2 * DM];
__device__ __nv_bfloat16 g_Woutb[(size_t)DM * DI];
__device__ __nv_bfloat16 g_Wxb[(size_t)NPROJ * DI];
__device__ __nv_bfloat16 g_Wdtb[(size_t)DI * DR];

// ---------------- helpers ----------------
__device__ __forceinline__ void cp_async16(void* dst_smem, const void* src, int src_bytes) {
    uint32_t d = (uint32_t)__cvta_generic_to_shared(dst_smem);
    asm volatile("cp.async.ca.shared.global [%0], [%1], 16, %2;\n"
                 :: "r"(d), "l"(src), "r"(src_bytes));
}
__device__ __forceinline__ void mma_bf16(float* c, const uint32_t* a, uint32_t b0, uint32_t b1) {
    asm volatile("mma.sync.aligned.m16n8k16.row.col.f32.bf16.bf16.f32 "
                 "{%0,%1,%2,%3}, {%4,%5,%6,%7}, {%8,%9}, {%0,%1,%2,%3};"
                 : "+f"(c[0]), "+f"(c[1]), "+f"(c[2]), "+f"(c[3])
                 : "r"(a[0]), "r"(a[1]), "r"(a[2]), "r"(a[3]), "r"(b0), "r"(b1));
}
__device__ __forceinline__ void ldm_x4(uint32_t* r, uint32_t addr) {
    asm volatile("ldmatrix.sync.aligned.m8n8.x4.shared.b16 {%0,%1,%2,%3}, [%4];"
                 : "=r"(r[0]), "=r"(r[1]), "=r"(r[2]), "=r"(r[3]) : "r"(addr));
}

// ---------------- fused preamble: LN + all weight converts + flag reset -------
#define N4_WIN  (D2 * DM / 4)
#define N4_WOUT (DM * DI / 4)
#define N4_WX   (NPROJ * DI / 4)
#define N4_WDT  (DI * DR / 4)
#define CV_TOTAL (N4_WIN + N4_WOUT + N4_WX + N4_WDT)
#define CV_BLOCKS ((CV_TOTAL + 255) / 256)
#define FLAG_BLOCKS ((BB * NC * 32 + 255) / 256)

__global__ void __launch_bounds__(256) preamble(const float* __restrict__ x,
                                                const float* __restrict__ gw,
                                                const float* __restrict__ bw,
                                                const float* __restrict__ Win,
                                                const float* __restrict__ Wout,
                                                const float* __restrict__ Wx,
                                                const float* __restrict__ Wdt) {
    int bid = blockIdx.x;
    int t = threadIdx.x;
    if (bid < MTOT) {
        // ---- LayerNorm row ----
        int row = bid;
        const float4* xr = (const float4*)(x + (size_t)row * DM);
        float4 xv = xr[t];
        float s = xv.x + xv.y + xv.z + xv.w;
        float sq = fmaf(xv.x, xv.x, fmaf(xv.y, xv.y, fmaf(xv.z, xv.z, xv.w * xv.w)));
        #pragma unroll
        for (int o = 16; o > 0; o >>= 1) {
            s  += __shfl_xor_sync(0xffffffffu, s, o);
            sq += __shfl_xor_sync(0xffffffffu, sq, o);
        }
        __shared__ float ss[8], ssq[8];
        int w = t >> 5;
        if ((t & 31) == 0) { ss[w] = s; ssq[w] = sq; }
        __syncthreads();
        if (t < 32) {
            s  = (t < 8) ? ss[t]  : 0.f;
            sq = (t < 8) ? ssq[t] : 0.f;
            #pragma unroll
            for (int o = 4; o > 0; o >>= 1) {
                s  += __shfl_xor_sync(0xffffffffu, s, o);
                sq += __shfl_xor_sync(0xffffffffu, sq, o);
            }
            if (t == 0) { ss[0] = s; ssq[0] = sq; }
        }
        __syncthreads();
        s = ss[0]; sq = ssq[0];
        float mu = s * (1.0f / DM);
        float var = sq * (1.0f / DM) - mu * mu;
        float rstd = rsqrtf(var + 1e-5f);
        float4 gv = ((const float4*)gw)[t];
        float4 bv = ((const float4*)bw)[t];
        __nv_bfloat162* dst = (__nv_bfloat162*)(g_hb + (size_t)row * DM);
        dst[t * 2]     = __floats2bfloat162_rn((xv.x - mu) * rstd * gv.x + bv.x,
                                               (xv.y - mu) * rstd * gv.y + bv.y);
        dst[t * 2 + 1] = __floats2bfloat162_rn((xv.z - mu) * rstd * gv.z + bv.z,
                                               (xv.w - mu) * rstd * gv.w + bv.w);
    } else if (bid < MTOT + CV_BLOCKS) {
        int i = (bid - MTOT) * 256 + t;
        const float* src;
        __nv_bfloat16* dst;
        int j;
        if (i < N4_WIN) { src = Win; dst = g_Winb; j = i; }
        else if (i < N4_WIN + N4_WOUT) { src = Wout; dst = g_Woutb; j = i - N4_WIN; }
        else if (i < N4_WIN + N4_WOUT + N4_WX) { src = Wx; dst = g_Wxb; j = i - N4_WIN - N4_WOUT; }
        else if (i < CV_TOTAL) { src = Wdt; dst = g_Wdtb; j = i - N4_WIN - N4_WOUT - N4_WX; }
        else return;
        float4 v = ((const float4*)src)[j];
        ((__nv_bfloat162*)dst)[j * 2]     = __floats2bfloat162_rn(v.x, v.y);
        ((__nv_bfloat162*)dst)[j * 2 + 1] = __floats2bfloat162_rn(v.z, v.w);
    } else {
        int f = (bid - MTOT - CV_BLOCKS) * 256 + t;
        if (f < BB * NC * 32) g_flag[f] = 0;
    }
}

// ---------------- BF16 GEMM, 2-stage, single barrier per chunk ----------------
template <int OUT, bool SPLIT>
__global__ void __launch_bounds__(256, 2) gemm_bf16(
    const __nv_bfloat16* __restrict__ A, int lda,
    const __nv_bfloat16* __restrict__ W, int ldw,
    const float* __restrict__ resid,
    void* __restrict__ Cout, int M, int Nld, int Nreal, int K)
{
    extern __shared__ float smf[];
    float* AsBase = smf;
    float* BsBase = smf + 2 * ASZ;
    uint32_t smemU = (uint32_t)__cvta_generic_to_shared(smf);
    int t = threadIdx.x;
    int lane = t & 31, warp = t >> 5;
    int wm = warp & 3, wn = warp >> 2;
    int m0 = blockIdx.y * 128, n0 = blockIdx.x * 128;
    if (SPLIT) {
        int z = blockIdx.z;
        A += (size_t)z * K;
        W += (size_t)z * K;
    }
    float* Cf = (float*)Cout + (SPLIT ? (size_t)blockIdx.z * M * Nld : 0);
    __nv_bfloat16* Cb = (__nv_bfloat16*)Cout;

    float acc[2][8][4];
    #pragma unroll
    for (int i = 0; i < 2; i++)
        #pragma unroll
        for (int j = 0; j < 8; j++)
            #pragma unroll
            for (int c = 0; c < 4; c++) acc[i][j][c] = 0.f;

    auto load_tiles = [&](int k0, int s) {
        const __nv_bfloat16* Ab = A + (size_t)m0 * lda + k0;
        const __nv_bfloat16* Wb = W + (size_t)n0 * ldw + k0;
        #pragma unroll
        for (int i = 0; i < 4; i++) {
            int idx = t + i * 256;
            int row = idx >> 3, seg = idx & 7;
            cp_async16(AsBase + s * ASZ + row * 36 + seg * 4,
                       Ab + (size_t)row * lda + seg * 8, 16);
            int ok = (n0 + row < Nreal) ? 16 : 0;
            cp_async16(BsBase + s * ASZ + row * 36 + seg * 4,
                       Wb + (size_t)(ok ? row : 0) * ldw + seg * 8, ok);
        }
        asm volatile("cp.async.commit_group;\n");
    };

    uint32_t aLane = ((uint32_t)(wm * 32 + (lane & 15)) * 36 + (((uint32_t)lane >> 4) << 2)) * 4;
    uint32_t bLane = ((uint32_t)(wn * 64 + (lane & 7) + ((lane & 16) ? 8 : 0)) * 36
                      + ((lane & 8) ? 4u : 0u)) * 4;

    const int nch = K >> 6;
    load_tiles(0, 0);

    int s = 0;
    for (int i = 0; i < nch; i++) {
        asm volatile("cp.async.wait_group 0;\n");
        __syncthreads();
        if (i + 1 < nch) load_tiles((i + 1) * 64, s ^ 1);
        uint32_t aStage = smemU + s * (ASZ * 4);
        uint32_t bStage = smemU + (2 + s) * (ASZ * 4);
        #pragma unroll
        for (int kk = 0; kk < 4; kk++) {
            uint32_t af[2][4];
            ldm_x4(af[0], aStage + aLane + kk * 32);
            ldm_x4(af[1], aStage + aLane + 2304 + kk * 32);
            #pragma unroll
            for (int fnp = 0; fnp < 4; fnp++) {
                uint32_t bf[4];
                ldm_x4(bf, bStage + bLane + fnp * 2304 + kk * 32);
                mma_bf16(acc[0][2 * fnp],     af[0], bf[0], bf[1]);
                mma_bf16(acc[1][2 * fnp],     af[1], bf[0], bf[1]);
                mma_bf16(acc[0][2 * fnp + 1], af[0], bf[2], bf[3]);
                mma_bf16(acc[1][2 * fnp + 1], af[1], bf[2], bf[3]);
            }
        }
        s ^= 1;
    }

    int r = lane >> 2;
    int c2 = (lane & 3) * 2;
    #pragma unroll
    for (int fm = 0; fm < 2; fm++) {
        #pragma unroll
        for (int fn = 0; fn < 8; fn++) {
            int gn = n0 + wn * 64 + fn * 8 + c2;
            #pragma unroll
            for (int hh = 0; hh < 2; hh++) {
                int gm = m0 + wm * 32 + fm * 16 + r + hh * 8;
                float v0 = acc[fm][fn][hh * 2 + 0];
                float v1 = acc[fm][fn][hh * 2 + 1];
                if (OUT == 2) {
                    v0 += resid[(size_t)gm * Nld + gn];
                    v1 += resid[(size_t)gm * Nld + gn + 1];
                }
                if (OUT == 3) {
                    v0 += resid[gn]; v1 += resid[gn + 1];   // bias
                    v0 = fmaxf(v0, 0.f) + __logf(1.f + __expf(-fabsf(v0)));
                    v1 = fmaxf(v1, 0.f) + __logf(1.f + __expf(-fabsf(v1)));
                }
                if (OUT == 1 || OUT == 3) {
                    *(__nv_bfloat162*)&Cb[(size_t)gm * Nld + gn] =
                        __floats2bfloat162_rn(v0, v1);
                } else {
                    *(float2*)&Cf[(size_t)gm * Nld + gn] = make_float2(v0, v1);
                }
            }
        }
    }
}

// ---------------- reduce x_proj split-K partials (f32 + bf16 dt slice) -------
__global__ void __launch_bounds__(256) reduce_proj() {
    int i = blockIdx.x * 256 + threadIdx.x;
    if (i >= MTOT * (NPROJ / 4)) return;
    int row = i / (NPROJ / 4);
    int c4 = (i % (NPROJ / 4)) * 4;
    size_t off = (size_t)row * NPAD + c4;
    const float* p = g_projp;
    const size_t stride = (size_t)MTOT * NPAD;
    float4 a = *(const float4*)&p[off];
    float4 b = *(const float4*)&p[off + stride];
    float4 c = *(const float4*)&p[off + 2 * stride];
    float4 d = *(const float4*)&p[off + 3 * stride];
    float4 o;
    o.x = a.x + b.x + c.x + d.x;
    o.y = a.y + b.y + c.y + d.y;
    o.z = a.z + b.z + c.z + d.z;
    o.w = a.w + b.w + c.w + d.w;
    *(float4*)&g_proj[(size_t)row * NPROJ + c4] = o;
    if (c4 < DR) {
        __nv_bfloat162* q = (__nv_bfloat162*)&g_pdtb[(size_t)row * DR + c4];
        q[0] = __floats2bfloat162_rn(o.x, o.y);
        q[1] = __floats2bfloat162_rn(o.z, o.w);
    }
}

// ---------------- causal conv1d + bias + SiLU (sliding window) ----------------
__global__ void __launch_bounds__(256) conv_kernel(const float* __restrict__ cw,
                                                   const float* __restrict__ cb) {
    int idx = blockIdx.x * 256 + threadIdx.x;
    if (idx >= (MTOT / CT) * 256) return;
    int cg = idx & 255;
    int mlb = idx >> 8;
    int lblk = mlb & (LL / CT - 1);
    int b = mlb >> 7;
    int l0 = lblk * CT;
    int cbase = cg * 8;
    size_t rowstep = D2;
    size_t rbase = ((size_t)(b * LL + l0)) * D2 + cbase;

    float bias[8];
    float wk[8][4];
    #pragma unroll
    for (int j = 0; j < 8; j++) {
        bias[j] = cb[cbase + j];
        float4 wv = ((const float4*)cw)[cbase + j];
        wk[j][0] = wv.x; wk[j][1] = wv.y; wk[j][2] = wv.z; wk[j][3] = wv.w;
    }

    float xh[3][8];
    #pragma unroll
    for (int k = 0; k < 3; k++) {
        int l = l0 - 3 + k;
        if (l >= 0) {
            uint4 raw = *(const uint4*)&g_xzb[rbase + (k - 3) * (long)rowstep];
            const __nv_bfloat162* bv = (const __nv_bfloat162*)&raw;
            #pragma unroll
            for (int j2 = 0; j2 < 4; j2++) {
                float2 f = __bfloat1622float2(bv[j2]);
                xh[k][j2 * 2] = f.x; xh[k][j2 * 2 + 1] = f.y;
            }
        } else {
            #pragma unroll
            for (int j = 0; j < 8; j++) xh[k][j] = 0.f;
        }
    }

    #pragma unroll
    for (int s = 0; s < CT; s++) {
        uint4 raw = *(const uint4*)&g_xzb[rbase + s * rowstep];
        const __nv_bfloat162* bv = (const __nv_bfloat162*)&raw;
        float xn[8];
        #pragma unroll
        for (int j2 = 0; j2 < 4; j2++) {
            float2 f = __bfloat1622float2(bv[j2]);
            xn[j2 * 2] = f.x; xn[j2 * 2 + 1] = f.y;
        }
        uint4 out;
        __nv_bfloat162* ov = (__nv_bfloat162*)&out;
        #pragma unroll
        for (int j2 = 0; j2 < 4; j2++) {
            float a0, a1;
            {
                int j = j2 * 2;
                a0 = bias[j];
                a0 = fmaf(xh[0][j], wk[j][0], a0);
                a0 = fmaf(xh[1][j], wk[j][1], a0);
                a0 = fmaf(xh[2][j], wk[j][2], a0);
                a0 = fmaf(xn[j],    wk[j][3], a0);
            }
            {
                int j = j2 * 2 + 1;
                a1 = bias[j];
                a1 = fmaf(xh[0][j], wk[j][0], a1);
                a1 = fmaf(xh[1][j], wk[j][1], a1);
                a1 = fmaf(xh[2][j], wk[j][2], a1);
                a1 = fmaf(xn[j],    wk[j][3], a1);
            }
            ov[j2] = __floats2bfloat162_rn(a0 / (1.f + __expf(-a0)),
                                           a1 / (1.f + __expf(-a1)));
        }
        *(uint4*)&g_ub[((size_t)(b * LL + l0 + s)) * DI + cbase] = out;
        #pragma unroll
        for (int j = 0; j < 8; j++) {
            xh[0][j] = xh[1][j];
            xh[1][j] = xh[2][j];
            xh[2][j] = xn[j];
        }
    }
}

// ---------------- fused selective scan (decoupled lookback) ----------------
// grid (DI/64, NC, BB), 128 threads. One kernel: local scan, lookback, emit.
__global__ void __launch_bounds__(128) scan_fused(const float* __restrict__ A_log,
                                                  const float* __restrict__ Dvec) {
    extern __shared__ float smf[];
    float* s_r  = smf;                                     // 4096 f
    float* s_bc = smf + 4096;                              // 2048 f
    __nv_bfloat16* s_w = (__nv_bfloat16*)(smf + 6144);     // 4096 bf16
    __nv_bfloat162* s_gu = (__nv_bfloat162*)(smf + 8192);  // 4096 bf16x2
    float* s_part = smf + 12288;                           // 128 f

    int dblk = blockIdx.x, chunk = blockIdx.y, b = blockIdx.z;
    int t = threadIdx.x;
    int d0 = dblk * 64;
    size_t base = (size_t)b * LL + (size_t)chunk * CH;

    // phase 0: load + transform
    {
        int chp = t & 63;
        int s0 = t >> 6;
        float Dd = Dvec[d0 + chp];
        float sdt_part = 0.f;
        #pragma unroll 8
        for (int sI = s0; sI < CH; sI += 2) {
            size_t off = (base + sI) * DI + d0 + chp;
            float dtv = __bfloat162float(g_dtb[off]);
            float uv  = __bfloat162float(g_ub[off]);
            float zv  = __bfloat162float(g_xzb[(base + sI) * D2 + DI + d0 + chp]);
            float gate = zv / (1.f + __expf(-zv));
            s_r[sI * 64 + chp] = __expf(-dtv);
            s_w[sI * 64 + chp] = __float2bfloat16(dtv * uv);
            s_gu[sI * 64 + chp] = __floats2bfloat162_rn(gate, uv * Dd * gate);
            sdt_part += dtv;
        }
        s_part[t] = sdt_part;
        #pragma unroll 4
        for (int i = t; i < CH * 32; i += 128) {
            int sI = i >> 5, j = i & 31;
            s_bc[sI * 32 + j] = g_proj[(base + sI) * NPROJ + DR + j];
        }
    }

    int half = t & 1, ch = t >> 1;
    int d = d0 + ch;
    float Areg[8];
    bool fastp = true;
    #pragma unroll
    for (int n = 0; n < 8; n++) {
        Areg[n] = -__expf(A_log[d * DS + half * 8 + n]);
        float tgt = (float)(half * 8 + n + 1);
        fastp = fastp && (fabsf(Areg[n] + tgt) < 1e-5f * tgt);
    }
    __syncthreads();
    float Sc = s_part[ch] + s_part[ch + 64];   // this chunk's dtsum for channel d

    // ---- pass 1: local scan (h0 = 0), B only ----
    float h[8];
    #pragma unroll
    for (int n = 0; n < 8; n++) h[n] = 0.f;
    if (fastp) {
        #pragma unroll 4
        for (int sI = 0; sI < CH; sI++) {
            float r = s_r[sI * 64 + ch];
            float w = __bfloat162float(s_w[sI * 64 + ch]);
            const float* bcr = s_bc + sI * 32 + half * 8;
            float4 b0 = *(const float4*)bcr;
            float4 b1 = *(const float4*)(bcr + 4);
            float r2 = r * r, r4 = r2 * r2, r8 = r4 * r4;
            float p = half ? r8 * r : r;
            h[0] = fmaf(p, h[0], w * b0.x); p *= r;
            h[1] = fmaf(p, h[1], w * b0.y); p *= r;
            h[2] = fmaf(p, h[2], w * b0.z); p *= r;
            h[3] = fmaf(p, h[3], w * b0.w); p *= r;
            h[4] = fmaf(p, h[4], w * b1.x); p *= r;
            h[5] = fmaf(p, h[5], w * b1.y); p *= r;
            h[6] = fmaf(p, h[6], w * b1.z); p *= r;
            h[7] = fmaf(p, h[7], w * b1.w);
        }
    } else {
        for (int sI = 0; sI < CH; sI++) {
            float r = s_r[sI * 64 + ch];
            float dtv = -__logf(r);
            float w = __bfloat162float(s_w[sI * 64 + ch]);
            #pragma unroll
            for (int n = 0; n < 8; n++) {
                float dA = __expf(dtv * Areg[n]);
                h[n] = fmaf(dA, h[n], w * s_bc[sI * 32 + half * 8 + n]);
            }
        }
    }

    // ---- publish local state ----
    size_t sb = ((size_t)(b * NC + chunk) * DI + d) * DS + half * 8;
    *(float4*)&g_state[sb]     = make_float4(h[0], h[1], h[2], h[3]);
    *(float4*)&g_state[sb + 4] = make_float4(h[4], h[5], h[6], h[7]);
    if (!half) g_dtsum[(size_t)(b * NC + chunk) * DI + d] = Sc;
    __threadfence();
    __syncthreads();
    int flagIdx = (b * NC + chunk) * 32 + dblk;
    if (t == 0) atomicExch(&g_flag[flagIdx], 1);

    // ---- lookback: h_start = sum_{j<chunk} hend_j * exp(A * S_{j+1..chunk-1}) ----
    float hs[8];
    #pragma unroll
    for (int n = 0; n < 8; n++) hs[n] = 0.f;
    float Ssum = 0.f;
    for (int j = chunk - 1; j >= 0; j--) {
        if (t == 0) {
            int fidx = (b * NC + j) * 32 + dblk;
            while (atomicAdd(&g_flag[fidx], 0) == 0) { }
        }
        __syncthreads();
        size_t jb = ((size_t)(b * NC + j) * DI + d) * DS + half * 8;
        float4 e0 = *(const float4*)&g_state[jb];
        float4 e1 = *(const float4*)&g_state[jb + 4];
        float Sj = g_dtsum[(size_t)(b * NC + j) * DI + d];
        float he[8] = {e0.x, e0.y, e0.z, e0.w, e1.x, e1.y, e1.z, e1.w};
        if (fastp) {
            float rr = __expf(-Ssum);
            float rr2 = rr * rr, rr4 = rr2 * rr2, rr8 = rr4 * rr4;
            float p = half ? rr8 * rr : rr;
            #pragma unroll
            for (int n = 0; n < 8; n++) {
                hs[n] = fmaf(p, he[n], hs[n]);
                p *= rr;
            }
        } else {
            #pragma unroll
            for (int n = 0; n < 8; n++) {
                float P = __expf(Areg[n] * Ssum);
                hs[n] = fmaf(P, he[n], hs[n]);
            }
        }
        Ssum += Sj;
    }

    // ---- pass 2: re-run from hs, emit y ----
    #pragma unroll
    for (int n = 0; n < 8; n++) h[n] = hs[n];
    if (fastp) {
        #pragma unroll 2
        for (int sI = 0; sI < CH; sI++) {
            float r = s_r[sI * 64 + ch];
            float w = __bfloat162float(s_w[sI * 64 + ch]);
            const float* bcr = s_bc + sI * 32 + half * 8;
            float4 b0 = *(const float4*)bcr;
            float4 b1 = *(const float4*)(bcr + 4);
            float4 c0 = *(const float4*)(bcr + 16);
            float4 c1 = *(const float4*)(bcr + 20);
            float r2 = r * r, r4 = r2 * r2, r8 = r4 * r4;
            float p = half ? r8 * r : r;
            float y;
            h[0] = fmaf(p, h[0], w * b0.x); y = h[0] * c0.x;          p *= r;
            h[1] = fmaf(p, h[1], w * b0.y); y = fmaf(h[1], c0.y, y);  p *= r;
            h[2] = fmaf(p, h[2], w * b0.z); y = fmaf(h[2], c0.z, y);  p *= r;
            h[3] = fmaf(p, h[3], w * b0.w); y = fmaf(h[3], c0.w, y);  p *= r;
            h[4] = fmaf(p, h[4], w * b1.x); y = fmaf(h[4], c1.x, y);  p *= r;
            h[5] = fmaf(p, h[5], w * b1.y); y = fmaf(h[5], c1.y, y);  p *= r;
            h[6] = fmaf(p, h[6], w * b1.z); y = fmaf(h[6], c1.z, y);  p *= r;
            h[7] = fmaf(p, h[7], w * b1.w); y = fmaf(h[7], c1.w, y);
            y += __shfl_xor_sync(0xffffffffu, y, 1);
            if (!half) {
                float2 g = __bfloat1622float2(s_gu[sI * 64 + ch]);
                g_ygb[(base + sI) * DI + d] = __float2bfloat16(fmaf(y, g.x, g.y));
            }
        }
    } else {
        for (int sI = 0; sI < CH; sI++) {
            float r = s_r[sI * 64 + ch];
            float dtv = -__logf(r);
            float w = __bfloat162float(s_w[sI * 64 + ch]);
            float y = 0.f;
            #pragma unroll
            for (int n = 0; n < 8; n++) {
                float dA = __expf(dtv * Areg[n]);
                h[n] = fmaf(dA, h[n], w * s_bc[sI * 32 + half * 8 + n]);
                y = fmaf(h[n], s_bc[sI * 32 + 16 + half * 8 + n], y);
            }
            y += __shfl_xor_sync(0xffffffffu, y, 1);
            if (!half) {
                float2 g = __bfloat1622float2(s_gu[sI * 64 + ch]);
                g_ygb[(base + sI) * DI + d] = __float2bfloat16(fmaf(y, g.x, g.y));
            }
        }
    }
}

// ---------------- launch ----------------
extern "C" void kernel_launch(void* const* d_in, const int* in_sizes, int n_in,
                              void* d_out, int out_size) {
    const float* x       = (const float*)d_in[0];
    const float* ln_g    = (const float*)d_in[1];
    const float* ln_b    = (const float*)d_in[2];
    const float* W_in    = (const float*)d_in[3];
    const float* conv_w  = (const float*)d_in[4];
    const float* conv_b  = (const float*)d_in[5];
    const float* W_xproj = (const float*)d_in[6];
    const float* W_dt    = (const float*)d_in[7];
    const float* b_dt    = (const float*)d_in[8];
    const float* A_log   = (const float*)d_in[9];
    const float* Dvec    = (const float*)d_in[10];
    const float* W_out   = (const float*)d_in[11];
    float* out = (float*)d_out;

    float *p_projp;
    __nv_bfloat16 *p_hb, *p_xzb, *p_ub, *p_dtb, *p_ygb, *p_Winb, *p_Woutb, *p_Wxb, *p_Wdtb, *p_pdtb;
    cudaGetSymbolAddress((void**)&p_projp, g_projp);
    cudaGetSymbolAddress((void**)&p_hb,    g_hb);
    cudaGetSymbolAddress((void**)&p_xzb,   g_xzb);
    cudaGetSymbolAddress((void**)&p_ub,    g_ub);
    cudaGetSymbolAddress((void**)&p_dtb,   g_dtb);
    cudaGetSymbolAddress((void**)&p_ygb,   g_ygb);
    cudaGetSymbolAddress((void**)&p_Winb,  g_Winb);
    cudaGetSymbolAddress((void**)&p_Woutb, g_Woutb);
    cudaGetSymbolAddress((void**)&p_Wxb,   g_Wxb);
    cudaGetSymbolAddress((void**)&p_Wdtb,  g_Wdtb);
    cudaGetSymbolAddress((void**)&p_pdtb,  g_pdtb);

    const int smem_bytes = 4 * ASZ * 4;   // 73728 (2-stage GEMM, 2 blocks/SM)
    const int scan_smem  = 12288 * 4 + 512;   // 49664
    cudaFuncSetAttribute((gemm_bf16<0,true>),  cudaFuncAttributeMaxDynamicSharedMemorySize, smem_bytes);
    cudaFuncSetAttribute((gemm_bf16<1,false>), cudaFuncAttributeMaxDynamicSharedMemorySize, smem_bytes);
    cudaFuncSetAttribute((gemm_bf16<2,false>), cudaFuncAttributeMaxDynamicSharedMemorySize, smem_bytes);
    cudaFuncSetAttribute((gemm_bf16<3,false>), cudaFuncAttributeMaxDynamicSharedMemorySize, smem_bytes);
    cudaFuncSetAttribute(scan_fused, cudaFuncAttributeMaxDynamicSharedMemorySize, scan_smem);

    // 1. preamble: LN + weight converts + flag reset
    preamble<<<MTOT + CV_BLOCKS + FLAG_BLOCKS, 256>>>(x, ln_g, ln_b, W_in, W_out, W_xproj, W_dt);

    // 2. in_proj: M=8192 N=4096 K=1024
    {
        dim3 grid(D2 / 128, MTOT / 128);
        gemm_bf16<1,false><<<grid, 256, smem_bytes>>>(p_hb, DM, p_Winb, DM, nullptr,
                                                      p_xzb, MTOT, D2, D2, DM);
    }

    // 3. conv + SiLU -> u
    conv_kernel<<<((MTOT / CT) * 256) / 256, 256>>>(conv_w, conv_b);

    // 4. x_proj (split-K x4): N=96 (padded 128), K=2048   ** profiled **
    {
        dim3 grid(1, MTOT / 128, KSPL);
        gemm_bf16<0,true><<<grid, 256, smem_bytes>>>(p_ub, DI, p_Wxb, DI, nullptr,
                                                     p_projp, MTOT, NPAD, NPROJ, DI / KSPL);
        reduce_proj<<<(MTOT * (NPROJ / 4) + 255) / 256, 256>>>();
    }

    // 5. dt (bias+softplus): M=8192 N=2048 K=64
    {
        dim3 grid(DI / 128, MTOT / 128);
        gemm_bf16<3,false><<<grid, 256, smem_bytes>>>(p_pdtb, DR, p_Wdtb, DR, b_dt,
                                                      p_dtb, MTOT, DI, DI, DR);
    }

    // 6. fused selective scan (decoupled lookback)
    {
        dim3 gridS(DI / 64, NC, BB);
        scan_fused<<<gridS, 128, scan_smem>>>(A_log, Dvec);
    }

    // 7. out_proj (f32 + resid): M=8192 N=1024 K=2048
    {
        dim3 grid(DM / 128, MTOT / 128);
        gemm_bf16<2,false><<<grid, 256, smem_bytes>>>(p_ygb, DI, p_Woutb, DI, x,
                                                      out, MTOT, DM, DM, DI);
    }
}

// round 16
// speedup vs baseline: 1.0118x; 1.0118x over previous
#include <cuda_runtime.h>
#include <cuda_bf16.h>
#include <math.h>
#include <stdint.h>

#define BB   4
#define LL   2048
#define DM   1024
#define DI   2048
#define D2   4096      // 2*DI
#define DS   16
#define DR   64
#define NPROJ 96       // DR + 2*DS
#define MTOT (BB*LL)   // 8192
#define ASZ  (128*36)  // one GEMM tile stage (words)
#define NC   32        // scan chunks
#define CH   64        // steps per chunk
#define KSPL 4         // x_proj K splits
#define NPAD 128       // x_proj partial leading dim
#define CT   16        // conv timesteps per thread

// ---------------- scratch ----------------
__device__ __nv_bfloat16 g_hb[(size_t)MTOT * DM];
__device__ __nv_bfloat16 g_xzb[(size_t)MTOT * D2];
__device__ __nv_bfloat16 g_ub[(size_t)MTOT * DI];
__device__ float g_proj[(size_t)MTOT * NPROJ];
__device__ __nv_bfloat16 g_pdtb[(size_t)MTOT * DR];
__device__ float g_projp[(size_t)KSPL * MTOT * NPAD];
__device__ __nv_bfloat16 g_dtb[(size_t)MTOT * DI];
__device__ __nv_bfloat16 g_ygb[(size_t)MTOT * DI];
__device__ float g_state[(size_t)BB * NC * DI * DS];
__device__ float g_dtsum[(size_t)BB * NC * DI];
__device__ __nv_bfloat16 g_Winb[(size_t)D2 * DM];
__device__ __nv_bfloat16 g_Woutb[(size_t)DM * DI];
__device__ __nv_bfloat16 g_Wxb[(size_t)NPROJ * DI];
__device__ __nv_bfloat16 g_Wdtb[(size_t)DI * DR];

// ---------------- helpers ----------------
__device__ __forceinline__ void cp_async16(void* dst_smem, const void* src, int src_bytes) {
    uint32_t d = (uint32_t)__cvta_generic_to_shared(dst_smem);
    asm volatile("cp.async.ca.shared.global [%0], [%1], 16, %2;\n"
                 :: "r"(d), "l"(src), "r"(src_bytes));
}
__device__ __forceinline__ void mma_bf16(float* c, const uint32_t* a, uint32_t b0, uint32_t b1) {
    asm volatile("mma.sync.aligned.m16n8k16.row.col.f32.bf16.bf16.f32 "
                 "{%0,%1,%2,%3}, {%4,%5,%6,%7}, {%8,%9}, {%0,%1,%2,%3};"
                 : "+f"(c[0]), "+f"(c[1]), "+f"(c[2]), "+f"(c[3])
                 : "r"(a[0]), "r"(a[1]), "r"(a[2]), "r"(a[3]), "r"(b0), "r"(b1));
}
__device__ __forceinline__ void ldm_x4(uint32_t* r, uint32_t addr) {
    asm volatile("ldmatrix.sync.aligned.m8n8.x4.shared.b16 {%0,%1,%2,%3}, [%4];"
                 : "=r"(r[0]), "=r"(r[1]), "=r"(r[2]), "=r"(r[3]) : "r"(addr));
}

// ---------------- fused preamble: LN + all weight converts ----------------
#define N4_WIN  (D2 * DM / 4)
#define N4_WOUT (DM * DI / 4)
#define N4_WX   (NPROJ * DI / 4)
#define N4_WDT  (DI * DR / 4)
#define CV_TOTAL (N4_WIN + N4_WOUT + N4_WX + N4_WDT)
#define CV_BLOCKS ((CV_TOTAL + 255) / 256)

__global__ void __launch_bounds__(256) preamble(const float* __restrict__ x,
                                                const float* __restrict__ gw,
                                                const float* __restrict__ bw,
                                                const float* __restrict__ Win,
                                                const float* __restrict__ Wout,
                                                const float* __restrict__ Wx,
                                                const float* __restrict__ Wdt) {
    int bid = blockIdx.x;
    int t = threadIdx.x;
    if (bid < MTOT) {
        // ---- LayerNorm row ----
        int row = bid;
        const float4* xr = (const float4*)(x + (size_t)row * DM);
        float4 xv = xr[t];
        float s = xv.x + xv.y + xv.z + xv.w;
        float sq = fmaf(xv.x, xv.x, fmaf(xv.y, xv.y, fmaf(xv.z, xv.z, xv.w * xv.w)));
        #pragma unroll
        for (int o = 16; o > 0; o >>= 1) {
            s  += __shfl_xor_sync(0xffffffffu, s, o);
            sq += __shfl_xor_sync(0xffffffffu, sq, o);
        }
        __shared__ float ss[8], ssq[8];
        int w = t >> 5;
        if ((t & 31) == 0) { ss[w] = s; ssq[w] = sq; }
        __syncthreads();
        if (t < 32) {
            s  = (t < 8) ? ss[t]  : 0.f;
            sq = (t < 8) ? ssq[t] : 0.f;
            #pragma unroll
            for (int o = 4; o > 0; o >>= 1) {
                s  += __shfl_xor_sync(0xffffffffu, s, o);
                sq += __shfl_xor_sync(0xffffffffu, sq, o);
            }
            if (t == 0) { ss[0] = s; ssq[0] = sq; }
        }
        __syncthreads();
        s = ss[0]; sq = ssq[0];
        float mu = s * (1.0f / DM);
        float var = sq * (1.0f / DM) - mu * mu;
        float rstd = rsqrtf(var + 1e-5f);
        float4 gv = ((const float4*)gw)[t];
        float4 bv = ((const float4*)bw)[t];
        __nv_bfloat162* dst = (__nv_bfloat162*)(g_hb + (size_t)row * DM);
        dst[t * 2]     = __floats2bfloat162_rn((xv.x - mu) * rstd * gv.x + bv.x,
                                               (xv.y - mu) * rstd * gv.y + bv.y);
        dst[t * 2 + 1] = __floats2bfloat162_rn((xv.z - mu) * rstd * gv.z + bv.z,
                                               (xv.w - mu) * rstd * gv.w + bv.w);
    } else {
        int i = (bid - MTOT) * 256 + t;
        const float* src;
        __nv_bfloat16* dst;
        int j;
        if (i < N4_WIN) { src = Win; dst = g_Winb; j = i; }
        else if (i < N4_WIN + N4_WOUT) { src = Wout; dst = g_Woutb; j = i - N4_WIN; }
        else if (i < N4_WIN + N4_WOUT + N4_WX) { src = Wx; dst = g_Wxb; j = i - N4_WIN - N4_WOUT; }
        else if (i < CV_TOTAL) { src = Wdt; dst = g_Wdtb; j = i - N4_WIN - N4_WOUT - N4_WX; }
        else return;
        float4 v = ((const float4*)src)[j];
        ((__nv_bfloat162*)dst)[j * 2]     = __floats2bfloat162_rn(v.x, v.y);
        ((__nv_bfloat162*)dst)[j * 2 + 1] = __floats2bfloat162_rn(v.z, v.w);
    }
}

// ---------------- BF16 GEMM, 2-stage, single barrier per chunk ----------------
// OUT 0: f32 out (SPLIT). OUT 1: bf16 out. OUT 2: f32 out + resid.
// OUT 3: bf16 out, +bias then softplus (bias via 'resid').
template <int OUT, bool SPLIT>
__global__ void __launch_bounds__(256, 2) gemm_bf16(
    const __nv_bfloat16* __restrict__ A, int lda,
    const __nv_bfloat16* __restrict__ W, int ldw,
    const float* __restrict__ resid,
    void* __restrict__ Cout, int M, int Nld, int Nreal, int K)
{
    extern __shared__ float smf[];
    float* AsBase = smf;
    float* BsBase = smf + 2 * ASZ;
    uint32_t smemU = (uint32_t)__cvta_generic_to_shared(smf);
    int t = threadIdx.x;
    int lane = t & 31, warp = t >> 5;
    int wm = warp & 3, wn = warp >> 2;
    int m0 = blockIdx.y * 128, n0 = blockIdx.x * 128;
    if (SPLIT) {
        int z = blockIdx.z;
        A += (size_t)z * K;
        W += (size_t)z * K;
    }
    float* Cf = (float*)Cout + (SPLIT ? (size_t)blockIdx.z * M * Nld : 0);
    __nv_bfloat16* Cb = (__nv_bfloat16*)Cout;

    float acc[2][8][4];
    #pragma unroll
    for (int i = 0; i < 2; i++)
        #pragma unroll
        for (int j = 0; j < 8; j++)
            #pragma unroll
            for (int c = 0; c < 4; c++) acc[i][j][c] = 0.f;

    auto load_tiles = [&](int k0, int s) {
        const __nv_bfloat16* Ab = A + (size_t)m0 * lda + k0;
        const __nv_bfloat16* Wb = W + (size_t)n0 * ldw + k0;
        #pragma unroll
        for (int i = 0; i < 4; i++) {
            int idx = t + i * 256;
            int row = idx >> 3, seg = idx & 7;
            cp_async16(AsBase + s * ASZ + row * 36 + seg * 4,
                       Ab + (size_t)row * lda + seg * 8, 16);
            int ok = (n0 + row < Nreal) ? 16 : 0;
            cp_async16(BsBase + s * ASZ + row * 36 + seg * 4,
                       Wb + (size_t)(ok ? row : 0) * ldw + seg * 8, ok);
        }
        asm volatile("cp.async.commit_group;\n");
    };

    uint32_t aLane = ((uint32_t)(wm * 32 + (lane & 15)) * 36 + (((uint32_t)lane >> 4) << 2)) * 4;
    uint32_t bLane = ((uint32_t)(wn * 64 + (lane & 7) + ((lane & 16) ? 8 : 0)) * 36
                      + ((lane & 8) ? 4u : 0u)) * 4;

    const int nch = K >> 6;
    load_tiles(0, 0);

    int s = 0;
    for (int i = 0; i < nch; i++) {
        asm volatile("cp.async.wait_group 0;\n");
        __syncthreads();
        if (i + 1 < nch) load_tiles((i + 1) * 64, s ^ 1);
        uint32_t aStage = smemU + s * (ASZ * 4);
        uint32_t bStage = smemU + (2 + s) * (ASZ * 4);
        #pragma unroll
        for (int kk = 0; kk < 4; kk++) {
            uint32_t af[2][4];
            ldm_x4(af[0], aStage + aLane + kk * 32);
            ldm_x4(af[1], aStage + aLane + 2304 + kk * 32);
            #pragma unroll
            for (int fnp = 0; fnp < 4; fnp++) {
                uint32_t bf[4];
                ldm_x4(bf, bStage + bLane + fnp * 2304 + kk * 32);
                mma_bf16(acc[0][2 * fnp],     af[0], bf[0], bf[1]);
                mma_bf16(acc[1][2 * fnp],     af[1], bf[0], bf[1]);
                mma_bf16(acc[0][2 * fnp + 1], af[0], bf[2], bf[3]);
                mma_bf16(acc[1][2 * fnp + 1], af[1], bf[2], bf[3]);
            }
        }
        s ^= 1;
    }

    int r = lane >> 2;
    int c2 = (lane & 3) * 2;
    #pragma unroll
    for (int fm = 0; fm < 2; fm++) {
        #pragma unroll
        for (int fn = 0; fn < 8; fn++) {
            int gn = n0 + wn * 64 + fn * 8 + c2;
            #pragma unroll
            for (int hh = 0; hh < 2; hh++) {
                int gm = m0 + wm * 32 + fm * 16 + r + hh * 8;
                float v0 = acc[fm][fn][hh * 2 + 0];
                float v1 = acc[fm][fn][hh * 2 + 1];
                if (OUT == 2) {
                    v0 += resid[(size_t)gm * Nld + gn];
                    v1 += resid[(size_t)gm * Nld + gn + 1];
                }
                if (OUT == 3) {
                    v0 += resid[gn]; v1 += resid[gn + 1];   // bias
                    v0 = fmaxf(v0, 0.f) + __logf(1.f + __expf(-fabsf(v0)));
                    v1 = fmaxf(v1, 0.f) + __logf(1.f + __expf(-fabsf(v1)));
                }
                if (OUT == 1 || OUT == 3) {
                    *(__nv_bfloat162*)&Cb[(size_t)gm * Nld + gn] =
                        __floats2bfloat162_rn(v0, v1);
                } else {
                    *(float2*)&Cf[(size_t)gm * Nld + gn] = make_float2(v0, v1);
                }
            }
        }
    }
}

// ---------------- reduce x_proj split-K partials (f32 + bf16 dt slice) -------
__global__ void __launch_bounds__(256) reduce_proj() {
    int i = blockIdx.x * 256 + threadIdx.x;
    if (i >= MTOT * (NPROJ / 4)) return;
    int row = i / (NPROJ / 4);
    int c4 = (i % (NPROJ / 4)) * 4;
    size_t off = (size_t)row * NPAD + c4;
    const float* p = g_projp;
    const size_t stride = (size_t)MTOT * NPAD;
    float4 a = *(const float4*)&p[off];
    float4 b = *(const float4*)&p[off + stride];
    float4 c = *(const float4*)&p[off + 2 * stride];
    float4 d = *(const float4*)&p[off + 3 * stride];
    float4 o;
    o.x = a.x + b.x + c.x + d.x;
    o.y = a.y + b.y + c.y + d.y;
    o.z = a.z + b.z + c.z + d.z;
    o.w = a.w + b.w + c.w + d.w;
    *(float4*)&g_proj[(size_t)row * NPROJ + c4] = o;
    if (c4 < DR) {
        __nv_bfloat162* q = (__nv_bfloat162*)&g_pdtb[(size_t)row * DR + c4];
        q[0] = __floats2bfloat162_rn(o.x, o.y);
        q[1] = __floats2bfloat162_rn(o.z, o.w);
    }
}

// ---------------- causal conv1d + bias + SiLU (sliding window) ----------------
__global__ void __launch_bounds__(256) conv_kernel(const float* __restrict__ cw,
                                                   const float* __restrict__ cb) {
    int idx = blockIdx.x * 256 + threadIdx.x;
    if (idx >= (MTOT / CT) * 256) return;
    int cg = idx & 255;
    int mlb = idx >> 8;
    int lblk = mlb & (LL / CT - 1);
    int b = mlb >> 7;
    int l0 = lblk * CT;
    int cbase = cg * 8;
    size_t rowstep = D2;
    size_t rbase = ((size_t)(b * LL + l0)) * D2 + cbase;

    float bias[8];
    float wk[8][4];
    #pragma unroll
    for (int j = 0; j < 8; j++) {
        bias[j] = cb[cbase + j];
        float4 wv = ((const float4*)cw)[cbase + j];
        wk[j][0] = wv.x; wk[j][1] = wv.y; wk[j][2] = wv.z; wk[j][3] = wv.w;
    }

    float xh[3][8];
    #pragma unroll
    for (int k = 0; k < 3; k++) {
        int l = l0 - 3 + k;
        if (l >= 0) {
            uint4 raw = *(const uint4*)&g_xzb[rbase + (k - 3) * (long)rowstep];
            const __nv_bfloat162* bv = (const __nv_bfloat162*)&raw;
            #pragma unroll
            for (int j2 = 0; j2 < 4; j2++) {
                float2 f = __bfloat1622float2(bv[j2]);
                xh[k][j2 * 2] = f.x; xh[k][j2 * 2 + 1] = f.y;
            }
        } else {
            #pragma unroll
            for (int j = 0; j < 8; j++) xh[k][j] = 0.f;
        }
    }

    #pragma unroll
    for (int s = 0; s < CT; s++) {
        uint4 raw = *(const uint4*)&g_xzb[rbase + s * rowstep];
        const __nv_bfloat162* bv = (const __nv_bfloat162*)&raw;
        float xn[8];
        #pragma unroll
        for (int j2 = 0; j2 < 4; j2++) {
            float2 f = __bfloat1622float2(bv[j2]);
            xn[j2 * 2] = f.x; xn[j2 * 2 + 1] = f.y;
        }
        uint4 out;
        __nv_bfloat162* ov = (__nv_bfloat162*)&out;
        #pragma unroll
        for (int j2 = 0; j2 < 4; j2++) {
            float a0, a1;
            {
                int j = j2 * 2;
                a0 = bias[j];
                a0 = fmaf(xh[0][j], wk[j][0], a0);
                a0 = fmaf(xh[1][j], wk[j][1], a0);
                a0 = fmaf(xh[2][j], wk[j][2], a0);
                a0 = fmaf(xn[j],    wk[j][3], a0);
            }
            {
                int j = j2 * 2 + 1;
                a1 = bias[j];
                a1 = fmaf(xh[0][j], wk[j][0], a1);
                a1 = fmaf(xh[1][j], wk[j][1], a1);
                a1 = fmaf(xh[2][j], wk[j][2], a1);
                a1 = fmaf(xn[j],    wk[j][3], a1);
            }
            ov[j2] = __floats2bfloat162_rn(a0 / (1.f + __expf(-a0)),
                                           a1 / (1.f + __expf(-a1)));
        }
        *(uint4*)&g_ub[((size_t)(b * LL + l0 + s)) * DI + cbase] = out;
        #pragma unroll
        for (int j = 0; j < 8; j++) {
            xh[0][j] = xh[1][j];
            xh[1][j] = xh[2][j];
            xh[2][j] = xn[j];
        }
    }
}

// ---------------- scan phase A ----------------
__global__ void __launch_bounds__(128) scanA(const float* __restrict__ A_log) {
    extern __shared__ float smf[];
    float* s_r  = smf;
    float* s_bc = smf + 4096;
    __nv_bfloat16* s_w = (__nv_bfloat16*)(smf + 5120);
    float* s_part = smf + 7168;

    int b = blockIdx.z, chunk = blockIdx.y;
    int t = threadIdx.x;
    int d0 = blockIdx.x * 64;
    size_t base = (size_t)b * LL + (size_t)chunk * CH;

    {
        int chp = t & 63;
        int s0 = t >> 6;
        float sdt_part = 0.f;
        #pragma unroll 8
        for (int sI = s0; sI < CH; sI += 2) {
            size_t off = (base + sI) * DI + d0 + chp;
            float dtv = __bfloat162float(g_dtb[off]);
            float uv  = __bfloat162float(g_ub[off]);
            s_r[sI * 64 + chp] = __expf(-dtv);
            s_w[sI * 64 + chp] = __float2bfloat16(dtv * uv);
            sdt_part += dtv;
        }
        s_part[t] = sdt_part;
        #pragma unroll 4
        for (int i = t; i < CH * 16; i += 128) {
            int sI = i >> 4, j = i & 15;
            s_bc[sI * 16 + j] = g_proj[(base + sI) * NPROJ + DR + j];
        }
    }

    int half = t & 1;
    int ch = t >> 1;
    int d = d0 + ch;
    float Areg[8];
    bool fastp = true;
    #pragma unroll
    for (int n = 0; n < 8; n++) {
        Areg[n] = -__expf(A_log[d * DS + half * 8 + n]);
        float tgt = (float)(half * 8 + n + 1);
        fastp = fastp && (fabsf(Areg[n] + tgt) < 1e-5f * tgt);
    }
    float h[8];
    #pragma unroll
    for (int n = 0; n < 8; n++) h[n] = 0.f;
    __syncthreads();

    if (fastp) {
        #pragma unroll 4
        for (int sI = 0; sI < CH; sI++) {
            float r = s_r[sI * 64 + ch];
            float w = __bfloat162float(s_w[sI * 64 + ch]);
            const float* bcr = s_bc + sI * 16 + half * 8;
            float4 b0 = *(const float4*)bcr;
            float4 b1 = *(const float4*)(bcr + 4);
            float r2 = r * r, r4 = r2 * r2, r8 = r4 * r4;
            float p = half ? r8 * r : r;
            h[0] = fmaf(p, h[0], w * b0.x); p *= r;
            h[1] = fmaf(p, h[1], w * b0.y); p *= r;
            h[2] = fmaf(p, h[2], w * b0.z); p *= r;
            h[3] = fmaf(p, h[3], w * b0.w); p *= r;
            h[4] = fmaf(p, h[4], w * b1.x); p *= r;
            h[5] = fmaf(p, h[5], w * b1.y); p *= r;
            h[6] = fmaf(p, h[6], w * b1.z); p *= r;
            h[7] = fmaf(p, h[7], w * b1.w);
        }
    } else {
        for (int sI = 0; sI < CH; sI++) {
            float r = s_r[sI * 64 + ch];
            float dtv = -__logf(r);
            float w = __bfloat162float(s_w[sI * 64 + ch]);
            #pragma unroll
            for (int n = 0; n < 8; n++) {
                float dA = __expf(dtv * Areg[n]);
                h[n] = fmaf(dA, h[n], w * s_bc[sI * 16 + half * 8 + n]);
            }
        }
    }
    size_t sb = ((size_t)(b * NC + chunk) * DI + d) * DS + half * 8;
    *(float4*)&g_state[sb]     = make_float4(h[0], h[1], h[2], h[3]);
    *(float4*)&g_state[sb + 4] = make_float4(h[4], h[5], h[6], h[7]);
    if (!half) g_dtsum[(size_t)(b * NC + chunk) * DI + d] = s_part[ch] + s_part[ch + 64];
}

// ---------------- scan phase B ----------------
__global__ void __launch_bounds__(256) scanB(const float* __restrict__ A_log) {
    int tid = blockIdx.x * 256 + threadIdx.x;
    int d = tid & (DI - 1);
    int b = tid >> 11;
    float Areg[16];
    #pragma unroll
    for (int n = 0; n < 16; n++) Areg[n] = -__expf(A_log[d * DS + n]);
    float h[16];
    #pragma unroll
    for (int n = 0; n < 16; n++) h[n] = 0.f;
    for (int c = 0; c < NC; c++) {
        size_t sb = ((size_t)(b * NC + c) * DI + d) * DS;
        float4 e0 = *(float4*)&g_state[sb];
        float4 e1 = *(float4*)&g_state[sb + 4];
        float4 e2 = *(float4*)&g_state[sb + 8];
        float4 e3 = *(float4*)&g_state[sb + 12];
        float hend[16] = {e0.x,e0.y,e0.z,e0.w, e1.x,e1.y,e1.z,e1.w,
                          e2.x,e2.y,e2.z,e2.w, e3.x,e3.y,e3.z,e3.w};
        *(float4*)&g_state[sb]      = make_float4(h[0], h[1], h[2], h[3]);
        *(float4*)&g_state[sb + 4]  = make_float4(h[4], h[5], h[6], h[7]);
        *(float4*)&g_state[sb + 8]  = make_float4(h[8], h[9], h[10], h[11]);
        *(float4*)&g_state[sb + 12] = make_float4(h[12], h[13], h[14], h[15]);
        float S = g_dtsum[(size_t)(b * NC + c) * DI + d];
        #pragma unroll
        for (int n = 0; n < 16; n++) {
            float P = __expf(Areg[n] * S);
            h[n] = fmaf(P, h[n], hend[n]);
        }
    }
}

// ---------------- scan phase C ----------------
__global__ void __launch_bounds__(128) scanC(const float* __restrict__ A_log,
                                             const float* __restrict__ Dvec) {
    extern __shared__ float smf[];
    float* s_r  = smf;
    float* s_bc = smf + 4096;
    __nv_bfloat16* s_w = (__nv_bfloat16*)(smf + 6144);
    __nv_bfloat162* s_gu = (__nv_bfloat162*)(smf + 8192);

    int b = blockIdx.z, chunk = blockIdx.y;
    int t = threadIdx.x;
    int d0 = blockIdx.x * 64;
    size_t base = (size_t)b * LL + (size_t)chunk * CH;

    {
        int chp = t & 63;
        int s0 = t >> 6;
        float Dd = Dvec[d0 + chp];
        #pragma unroll 8
        for (int sI = s0; sI < CH; sI += 2) {
            size_t off = (base + sI) * DI + d0 + chp;
            float dtv = __bfloat162float(g_dtb[off]);
            float uv  = __bfloat162float(g_ub[off]);
            float zv  = __bfloat162float(g_xzb[(base + sI) * D2 + DI + d0 + chp]);
            float gate = zv / (1.f + __expf(-zv));
            s_r[sI * 64 + chp] = __expf(-dtv);
            s_w[sI * 64 + chp] = __float2bfloat16(dtv * uv);
            s_gu[sI * 64 + chp] = __floats2bfloat162_rn(gate, uv * Dd * gate);
        }
        #pragma unroll 4
        for (int i = t; i < CH * 32; i += 128) {
            int sI = i >> 5, j = i & 31;
            s_bc[sI * 32 + j] = g_proj[(base + sI) * NPROJ + DR + j];
        }
    }

    int half = t & 1, ch = t >> 1;
    int d = d0 + ch;
    float Areg[8];
    bool fastp = true;
    #pragma unroll
    for (int n = 0; n < 8; n++) {
        Areg[n] = -__expf(A_log[d * DS + half * 8 + n]);
        float tgt = (float)(half * 8 + n + 1);
        fastp = fastp && (fabsf(Areg[n] + tgt) < 1e-5f * tgt);
    }
    size_t sb = ((size_t)(b * NC + chunk) * DI + d) * DS + half * 8;
    float4 h0 = *(float4*)&g_state[sb];
    float4 h1 = *(float4*)&g_state[sb + 4];
    float h[8] = {h0.x, h0.y, h0.z, h0.w, h1.x, h1.y, h1.z, h1.w};
    __syncthreads();

    if (fastp) {
        #pragma unroll 2
        for (int sI = 0; sI < CH; sI++) {
            float r = s_r[sI * 64 + ch];
            float w = __bfloat162float(s_w[sI * 64 + ch]);
            const float* bcr = s_bc + sI * 32 + half * 8;
            float4 b0 = *(const float4*)bcr;
            float4 b1 = *(const float4*)(bcr + 4);
            float4 c0 = *(const float4*)(bcr + 16);
            float4 c1 = *(const float4*)(bcr + 20);
            float r2 = r * r, r4 = r2 * r2, r8 = r4 * r4;
            float p = half ? r8 * r : r;
            float y;
            h[0] = fmaf(p, h[0], w * b0.x); y = h[0] * c0.x;          p *= r;
            h[1] = fmaf(p, h[1], w * b0.y); y = fmaf(h[1], c0.y, y);  p *= r;
            h[2] = fmaf(p, h[2], w * b0.z); y = fmaf(h[2], c0.z, y);  p *= r;
            h[3] = fmaf(p, h[3], w * b0.w); y = fmaf(h[3], c0.w, y);  p *= r;
            h[4] = fmaf(p, h[4], w * b1.x); y = fmaf(h[4], c1.x, y);  p *= r;
            h[5] = fmaf(p, h[5], w * b1.y); y = fmaf(h[5], c1.y, y);  p *= r;
            h[6] = fmaf(p, h[6], w * b1.z); y = fmaf(h[6], c1.z, y);  p *= r;
            h[7] = fmaf(p, h[7], w * b1.w); y = fmaf(h[7], c1.w, y);
            y += __shfl_xor_sync(0xffffffffu, y, 1);
            if (!half) {
                float2 g = __bfloat1622float2(s_gu[sI * 64 + ch]);
                g_ygb[(base + sI) * DI + d] = __float2bfloat16(fmaf(y, g.x, g.y));
            }
        }
    } else {
        for (int sI = 0; sI < CH; sI++) {
            float r = s_r[sI * 64 + ch];
            float dtv = -__logf(r);
            float w = __bfloat162float(s_w[sI * 64 + ch]);
            float y = 0.f;
            #pragma unroll
            for (int n = 0; n < 8; n++) {
                float dA = __expf(dtv * Areg[n]);
                h[n] = fmaf(dA, h[n], w * s_bc[sI * 32 + half * 8 + n]);
                y = fmaf(h[n], s_bc[sI * 32 + 16 + half * 8 + n], y);
            }
            y += __shfl_xor_sync(0xffffffffu, y, 1);
            if (!half) {
                float2 g = __bfloat1622float2(s_gu[sI * 64 + ch]);
                g_ygb[(base + sI) * DI + d] = __float2bfloat16(fmaf(y, g.x, g.y));
            }
        }
    }
}

// ---------------- launch ----------------
extern "C" void kernel_launch(void* const* d_in, const int* in_sizes, int n_in,
                              void* d_out, int out_size) {
    const float* x       = (const float*)d_in[0];
    const float* ln_g    = (const float*)d_in[1];
    const float* ln_b    = (const float*)d_in[2];
    const float* W_in    = (const float*)d_in[3];
    const float* conv_w  = (const float*)d_in[4];
    const float* conv_b  = (const float*)d_in[5];
    const float* W_xproj = (const float*)d_in[6];
    const float* W_dt    = (const float*)d_in[7];
    const float* b_dt    = (const float*)d_in[8];
    const float* A_log   = (const float*)d_in[9];
    const float* Dvec    = (const float*)d_in[10];
    const float* W_out   = (const float*)d_in[11];
    float* out = (float*)d_out;

    float *p_projp;
    __nv_bfloat16 *p_hb, *p_xzb, *p_ub, *p_dtb, *p_ygb, *p_Winb, *p_Woutb, *p_Wxb, *p_Wdtb, *p_pdtb;
    cudaGetSymbolAddress((void**)&p_projp, g_projp);
    cudaGetSymbolAddress((void**)&p_hb,    g_hb);
    cudaGetSymbolAddress((void**)&p_xzb,   g_xzb);
    cudaGetSymbolAddress((void**)&p_ub,    g_ub);
    cudaGetSymbolAddress((void**)&p_dtb,   g_dtb);
    cudaGetSymbolAddress((void**)&p_ygb,   g_ygb);
    cudaGetSymbolAddress((void**)&p_Winb,  g_Winb);
    cudaGetSymbolAddress((void**)&p_Woutb, g_Woutb);
    cudaGetSymbolAddress((void**)&p_Wxb,   g_Wxb);
    cudaGetSymbolAddress((void**)&p_Wdtb,  g_Wdtb);
    cudaGetSymbolAddress((void**)&p_pdtb,  g_pdtb);

    const int smem_bytes = 4 * ASZ * 4;   // 73728 (2-stage GEMM, 2 blocks/SM)
    cudaFuncSetAttribute((gemm_bf16<0,true>),  cudaFuncAttributeMaxDynamicSharedMemorySize, smem_bytes);
    cudaFuncSetAttribute((gemm_bf16<1,false>), cudaFuncAttributeMaxDynamicSharedMemorySize, smem_bytes);
    cudaFuncSetAttribute((gemm_bf16<2,false>), cudaFuncAttributeMaxDynamicSharedMemorySize, smem_bytes);
    cudaFuncSetAttribute((gemm_bf16<3,false>), cudaFuncAttributeMaxDynamicSharedMemorySize, smem_bytes);
    cudaFuncSetAttribute(scanA, cudaFuncAttributeMaxDynamicSharedMemorySize, 29184);
    cudaFuncSetAttribute(scanC, cudaFuncAttributeMaxDynamicSharedMemorySize, 49152);

    // 1. fused preamble: LN + weight converts
    preamble<<<MTOT + CV_BLOCKS, 256>>>(x, ln_g, ln_b, W_in, W_out, W_xproj, W_dt);

    // 2. in_proj: M=8192 N=4096 K=1024
    {
        dim3 grid(D2 / 128, MTOT / 128);
        gemm_bf16<1,false><<<grid, 256, smem_bytes>>>(p_hb, DM, p_Winb, DM, nullptr,
                                                      p_xzb, MTOT, D2, D2, DM);
    }

    // 3. conv + SiLU -> u
    conv_kernel<<<((MTOT / CT) * 256) / 256, 256>>>(conv_w, conv_b);

    // 4. x_proj (split-K x4): N=96 (padded 128), K=2048
    {
        dim3 grid(1, MTOT / 128, KSPL);
        gemm_bf16<0,true><<<grid, 256, smem_bytes>>>(p_ub, DI, p_Wxb, DI, nullptr,
                                                     p_projp, MTOT, NPAD, NPROJ, DI / KSPL);
        reduce_proj<<<(MTOT * (NPROJ / 4) + 255) / 256, 256>>>();
    }

    // 5. dt (bias+softplus): M=8192 N=2048 K=64
    {
        dim3 grid(DI / 128, MTOT / 128);
        gemm_bf16<3,false><<<grid, 256, smem_bytes>>>(p_pdtb, DR, p_Wdtb, DR, b_dt,
                                                      p_dtb, MTOT, DI, DI, DR);
    }

    // 6. chunked selective scan (3-phase)
    {
        dim3 gridA(DI / 64, NC, BB);
        scanA<<<gridA, 128, 29184>>>(A_log);
        scanB<<<(BB * DI) / 256, 256>>>(A_log);
        scanC<<<gridA, 128, 49152>>>(A_log, Dvec);
    }

    // 7. out_proj (f32 + resid): M=8192 N=1024 K=2048
    {
        dim3 grid(DM / 128, MTOT / 128);
        gemm_bf16<2,false><<<grid, 256, smem_bytes>>>(p_ygb, DI, p_Woutb, DI, x,
                                                      out, MTOT, DM, DM, DI);
    }
}

// round 17
// speedup vs baseline: 1.0159x; 1.0040x over previous
#include <cuda_runtime.h>
#include <cuda_bf16.h>
#include <math.h>
#include <stdint.h>

#define BB   4
#define LL   2048
#define DM   1024
#define DI   2048
#define D2   4096      // 2*DI
#define DS   16
#define DR   64
#define NPROJ 96       // DR + 2*DS
#define MTOT (BB*LL)   // 8192
#define ASZ  (128*36)  // one GEMM tile stage (words)
#define NC   32        // scan chunks
#define CH   64        // steps per chunk
#define KSPL 4         // x_proj K splits
#define NPAD 128       // x_proj partial leading dim
#define CT   16        // conv timesteps per thread

// ---------------- scratch ----------------
__device__ __nv_bfloat16 g_hb[(size_t)MTOT * DM];
__device__ __nv_bfloat16 g_xzb[(size_t)MTOT * D2];
__device__ __nv_bfloat16 g_ub[(size_t)MTOT * DI];
__device__ float g_proj[(size_t)MTOT * NPROJ];
__device__ __nv_bfloat16 g_pdtb[(size_t)MTOT * DR];
__device__ float g_projp[(size_t)KSPL * MTOT * NPAD];
__device__ __nv_bfloat16 g_dtb[(size_t)MTOT * DI];
__device__ __nv_bfloat16 g_ygb[(size_t)MTOT * DI];
__device__ float g_state[(size_t)BB * NC * DI * DS];
__device__ float g_dtsum[(size_t)BB * NC * DI];
__device__ __nv_bfloat16 g_Winb[(size_t)D2 * DM];
__device__ __nv_bfloat16 g_Woutb[(size_t)DM * DI];
__device__ __nv_bfloat16 g_Wxb[(size_t)NPROJ * DI];
__device__ __nv_bfloat16 g_Wdtb[(size_t)DI * DR];

// ---------------- helpers ----------------
__device__ __forceinline__ void cp_async16(void* dst_smem, const void* src, int src_bytes) {
    uint32_t d = (uint32_t)__cvta_generic_to_shared(dst_smem);
    asm volatile("cp.async.ca.shared.global [%0], [%1], 16, %2;\n"
                 :: "r"(d), "l"(src), "r"(src_bytes));
}
__device__ __forceinline__ void mma_bf16(float* c, const uint32_t* a, uint32_t b0, uint32_t b1) {
    asm volatile("mma.sync.aligned.m16n8k16.row.col.f32.bf16.bf16.f32 "
                 "{%0,%1,%2,%3}, {%4,%5,%6,%7}, {%8,%9}, {%0,%1,%2,%3};"
                 : "+f"(c[0]), "+f"(c[1]), "+f"(c[2]), "+f"(c[3])
                 : "r"(a[0]), "r"(a[1]), "r"(a[2]), "r"(a[3]), "r"(b0), "r"(b1));
}
__device__ __forceinline__ void ldm_x4(uint32_t* r, uint32_t addr) {
    asm volatile("ldmatrix.sync.aligned.m8n8.x4.shared.b16 {%0,%1,%2,%3}, [%4];"
                 : "=r"(r[0]), "=r"(r[1]), "=r"(r[2]), "=r"(r[3]) : "r"(addr));
}

// ---------------- weight conversions ----------------
#define N4_WIN  (D2 * DM / 4)
#define N4_WOUT (DM * DI / 4)
#define N4_WX   (NPROJ * DI / 4)
#define N4_WDT  (DI * DR / 4)
__global__ void __launch_bounds__(256) convert_win(const float* __restrict__ Win) {
    int i = blockIdx.x * 256 + threadIdx.x;
    if (i >= N4_WIN) return;
    float4 v = ((const float4*)Win)[i];
    ((__nv_bfloat162*)g_Winb)[i * 2]     = __floats2bfloat162_rn(v.x, v.y);
    ((__nv_bfloat162*)g_Winb)[i * 2 + 1] = __floats2bfloat162_rn(v.z, v.w);
}
__global__ void __launch_bounds__(256) convert_rest(const float* __restrict__ Wout,
                                                    const float* __restrict__ Wx,
                                                    const float* __restrict__ Wdt) {
    int i = blockIdx.x * 256 + threadIdx.x;
    const float* src;
    __nv_bfloat16* dst;
    int j;
    if (i < N4_WOUT) { src = Wout; dst = g_Woutb; j = i; }
    else if (i < N4_WOUT + N4_WX) { src = Wx; dst = g_Wxb; j = i - N4_WOUT; }
    else if (i < N4_WOUT + N4_WX + N4_WDT) { src = Wdt; dst = g_Wdtb; j = i - N4_WOUT - N4_WX; }
    else return;
    float4 v = ((const float4*)src)[j];
    ((__nv_bfloat162*)dst)[j * 2]     = __floats2bfloat162_rn(v.x, v.y);
    ((__nv_bfloat162*)dst)[j * 2 + 1] = __floats2bfloat162_rn(v.z, v.w);
}

// ---------------- LayerNorm (bf16 output) ----------------
__global__ void __launch_bounds__(256) ln_kernel(const float* __restrict__ x,
                                                 const float* __restrict__ gw,
                                                 const float* __restrict__ bw) {
    int row = blockIdx.x;
    int t = threadIdx.x;
    const float4* xr = (const float4*)(x + (size_t)row * DM);
    float4 xv = xr[t];
    float s = xv.x + xv.y + xv.z + xv.w;
    float sq = fmaf(xv.x, xv.x, fmaf(xv.y, xv.y, fmaf(xv.z, xv.z, xv.w * xv.w)));
    #pragma unroll
    for (int o = 16; o > 0; o >>= 1) {
        s  += __shfl_xor_sync(0xffffffffu, s, o);
        sq += __shfl_xor_sync(0xffffffffu, sq, o);
    }
    __shared__ float ss[8], ssq[8];
    int w = t >> 5;
    if ((t & 31) == 0) { ss[w] = s; ssq[w] = sq; }
    __syncthreads();
    if (t < 32) {
        s  = (t < 8) ? ss[t]  : 0.f;
        sq = (t < 8) ? ssq[t] : 0.f;
        #pragma unroll
        for (int o = 4; o > 0; o >>= 1) {
            s  += __shfl_xor_sync(0xffffffffu, s, o);
            sq += __shfl_xor_sync(0xffffffffu, sq, o);
        }
        if (t == 0) { ss[0] = s; ssq[0] = sq; }
    }
    __syncthreads();
    s = ss[0]; sq = ssq[0];
    float mu = s * (1.0f / DM);
    float var = sq * (1.0f / DM) - mu * mu;
    float rstd = rsqrtf(var + 1e-5f);
    float4 gv = ((const float4*)gw)[t];
    float4 bv = ((const float4*)bw)[t];
    __nv_bfloat162* dst = (__nv_bfloat162*)(g_hb + (size_t)row * DM);
    dst[t * 2]     = __floats2bfloat162_rn((xv.x - mu) * rstd * gv.x + bv.x,
                                           (xv.y - mu) * rstd * gv.y + bv.y);
    dst[t * 2 + 1] = __floats2bfloat162_rn((xv.z - mu) * rstd * gv.z + bv.z,
                                           (xv.w - mu) * rstd * gv.w + bv.w);
}

// ---------------- BF16 GEMM, 2-stage, single barrier per chunk ----------------
// OUT 0: f32 out (SPLIT). OUT 1: bf16 out. OUT 2: f32 out + resid.
// OUT 3: bf16 out, +bias then softplus (bias via 'resid').
template <int OUT, bool SPLIT>
__global__ void __launch_bounds__(256, 2) gemm_bf16(
    const __nv_bfloat16* __restrict__ A, int lda,
    const __nv_bfloat16* __restrict__ W, int ldw,
    const float* __restrict__ resid,
    void* __restrict__ Cout, int M, int Nld, int Nreal, int K)
{
    extern __shared__ float smf[];
    float* AsBase = smf;
    float* BsBase = smf + 2 * ASZ;
    uint32_t smemU = (uint32_t)__cvta_generic_to_shared(smf);
    int t = threadIdx.x;
    int lane = t & 31, warp = t >> 5;
    int wm = warp & 3, wn = warp >> 2;
    int m0 = blockIdx.y * 128, n0 = blockIdx.x * 128;
    if (SPLIT) {
        int z = blockIdx.z;
        A += (size_t)z * K;
        W += (size_t)z * K;
    }
    float* Cf = (float*)Cout + (SPLIT ? (size_t)blockIdx.z * M * Nld : 0);
    __nv_bfloat16* Cb = (__nv_bfloat16*)Cout;

    float acc[2][8][4];
    #pragma unroll
    for (int i = 0; i < 2; i++)
        #pragma unroll
        for (int j = 0; j < 8; j++)
            #pragma unroll
            for (int c = 0; c < 4; c++) acc[i][j][c] = 0.f;

    auto load_tiles = [&](int k0, int s) {
        const __nv_bfloat16* Ab = A + (size_t)m0 * lda + k0;
        const __nv_bfloat16* Wb = W + (size_t)n0 * ldw + k0;
        #pragma unroll
        for (int i = 0; i < 4; i++) {
            int idx = t + i * 256;
            int row = idx >> 3, seg = idx & 7;
            cp_async16(AsBase + s * ASZ + row * 36 + seg * 4,
                       Ab + (size_t)row * lda + seg * 8, 16);
            int ok = (n0 + row < Nreal) ? 16 : 0;
            cp_async16(BsBase + s * ASZ + row * 36 + seg * 4,
                       Wb + (size_t)(ok ? row : 0) * ldw + seg * 8, ok);
        }
        asm volatile("cp.async.commit_group;\n");
    };

    uint32_t aLane = ((uint32_t)(wm * 32 + (lane & 15)) * 36 + (((uint32_t)lane >> 4) << 2)) * 4;
    uint32_t bLane = ((uint32_t)(wn * 64 + (lane & 7) + ((lane & 16) ? 8 : 0)) * 36
                      + ((lane & 8) ? 4u : 0u)) * 4;

    const int nch = K >> 6;
    load_tiles(0, 0);

    int s = 0;
    for (int i = 0; i < nch; i++) {
        asm volatile("cp.async.wait_group 0;\n");
        __syncthreads();
        if (i + 1 < nch) load_tiles((i + 1) * 64, s ^ 1);
        uint32_t aStage = smemU + s * (ASZ * 4);
        uint32_t bStage = smemU + (2 + s) * (ASZ * 4);
        #pragma unroll
        for (int kk = 0; kk < 4; kk++) {
            uint32_t af[2][4];
            ldm_x4(af[0], aStage + aLane + kk * 32);
            ldm_x4(af[1], aStage + aLane + 2304 + kk * 32);
            #pragma unroll
            for (int fnp = 0; fnp < 4; fnp++) {
                uint32_t bf[4];
                ldm_x4(bf, bStage + bLane + fnp * 2304 + kk * 32);
                mma_bf16(acc[0][2 * fnp],     af[0], bf[0], bf[1]);
                mma_bf16(acc[1][2 * fnp],     af[1], bf[0], bf[1]);
                mma_bf16(acc[0][2 * fnp + 1], af[0], bf[2], bf[3]);
                mma_bf16(acc[1][2 * fnp + 1], af[1], bf[2], bf[3]);
            }
        }
        s ^= 1;
    }

    int r = lane >> 2;
    int c2 = (lane & 3) * 2;
    #pragma unroll
    for (int fm = 0; fm < 2; fm++) {
        #pragma unroll
        for (int fn = 0; fn < 8; fn++) {
            int gn = n0 + wn * 64 + fn * 8 + c2;
            #pragma unroll
            for (int hh = 0; hh < 2; hh++) {
                int gm = m0 + wm * 32 + fm * 16 + r + hh * 8;
                float v0 = acc[fm][fn][hh * 2 + 0];
                float v1 = acc[fm][fn][hh * 2 + 1];
                if (OUT == 2) {
                    v0 += resid[(size_t)gm * Nld + gn];
                    v1 += resid[(size_t)gm * Nld + gn + 1];
                }
                if (OUT == 3) {
                    v0 += resid[gn]; v1 += resid[gn + 1];   // bias
                    v0 = fmaxf(v0, 0.f) + __logf(1.f + __expf(-fabsf(v0)));
                    v1 = fmaxf(v1, 0.f) + __logf(1.f + __expf(-fabsf(v1)));
                }
                if (OUT == 1 || OUT == 3) {
                    *(__nv_bfloat162*)&Cb[(size_t)gm * Nld + gn] =
                        __floats2bfloat162_rn(v0, v1);
                } else {
                    *(float2*)&Cf[(size_t)gm * Nld + gn] = make_float2(v0, v1);
                }
            }
        }
    }
}

// ---------------- reduce x_proj split-K partials (f32 + bf16 dt slice) -------
__global__ void __launch_bounds__(256) reduce_proj() {
    int i = blockIdx.x * 256 + threadIdx.x;
    if (i >= MTOT * (NPROJ / 4)) return;
    int row = i / (NPROJ / 4);
    int c4 = (i % (NPROJ / 4)) * 4;
    size_t off = (size_t)row * NPAD + c4;
    const float* p = g_projp;
    const size_t stride = (size_t)MTOT * NPAD;
    float4 a = *(const float4*)&p[off];
    float4 b = *(const float4*)&p[off + stride];
    float4 c = *(const float4*)&p[off + 2 * stride];
    float4 d = *(const float4*)&p[off + 3 * stride];
    float4 o;
    o.x = a.x + b.x + c.x + d.x;
    o.y = a.y + b.y + c.y + d.y;
    o.z = a.z + b.z + c.z + d.z;
    o.w = a.w + b.w + c.w + d.w;
    *(float4*)&g_proj[(size_t)row * NPROJ + c4] = o;
    if (c4 < DR) {
        __nv_bfloat162* q = (__nv_bfloat162*)&g_pdtb[(size_t)row * DR + c4];
        q[0] = __floats2bfloat162_rn(o.x, o.y);
        q[1] = __floats2bfloat162_rn(o.z, o.w);
    }
}

// ---------------- causal conv1d + bias + SiLU (sliding window) ----------------
__global__ void __launch_bounds__(256) conv_kernel(const float* __restrict__ cw,
                                                   const float* __restrict__ cb) {
    int idx = blockIdx.x * 256 + threadIdx.x;
    if (idx >= (MTOT / CT) * 256) return;
    int cg = idx & 255;
    int mlb = idx >> 8;
    int lblk = mlb & (LL / CT - 1);
    int b = mlb >> 7;
    int l0 = lblk * CT;
    int cbase = cg * 8;
    size_t rowstep = D2;
    size_t rbase = ((size_t)(b * LL + l0)) * D2 + cbase;

    float bias[8];
    float wk[8][4];
    #pragma unroll
    for (int j = 0; j < 8; j++) {
        bias[j] = cb[cbase + j];
        float4 wv = ((const float4*)cw)[cbase + j];
        wk[j][0] = wv.x; wk[j][1] = wv.y; wk[j][2] = wv.z; wk[j][3] = wv.w;
    }

    float xh[3][8];
    #pragma unroll
    for (int k = 0; k < 3; k++) {
        int l = l0 - 3 + k;
        if (l >= 0) {
            uint4 raw = *(const uint4*)&g_xzb[rbase + (k - 3) * (long)rowstep];
            const __nv_bfloat162* bv = (const __nv_bfloat162*)&raw;
            #pragma unroll
            for (int j2 = 0; j2 < 4; j2++) {
                float2 f = __bfloat1622float2(bv[j2]);
                xh[k][j2 * 2] = f.x; xh[k][j2 * 2 + 1] = f.y;
            }
        } else {
            #pragma unroll
            for (int j = 0; j < 8; j++) xh[k][j] = 0.f;
        }
    }

    #pragma unroll
    for (int s = 0; s < CT; s++) {
        uint4 raw = *(const uint4*)&g_xzb[rbase + s * rowstep];
        const __nv_bfloat162* bv = (const __nv_bfloat162*)&raw;
        float xn[8];
        #pragma unroll
        for (int j2 = 0; j2 < 4; j2++) {
            float2 f = __bfloat1622float2(bv[j2]);
            xn[j2 * 2] = f.x; xn[j2 * 2 + 1] = f.y;
        }
        uint4 out;
        __nv_bfloat162* ov = (__nv_bfloat162*)&out;
        #pragma unroll
        for (int j2 = 0; j2 < 4; j2++) {
            float a0, a1;
            {
                int j = j2 * 2;
                a0 = bias[j];
                a0 = fmaf(xh[0][j], wk[j][0], a0);
                a0 = fmaf(xh[1][j], wk[j][1], a0);
                a0 = fmaf(xh[2][j], wk[j][2], a0);
                a0 = fmaf(xn[j],    wk[j][3], a0);
            }
            {
                int j = j2 * 2 + 1;
                a1 = bias[j];
                a1 = fmaf(xh[0][j], wk[j][0], a1);
                a1 = fmaf(xh[1][j], wk[j][1], a1);
                a1 = fmaf(xh[2][j], wk[j][2], a1);
                a1 = fmaf(xn[j],    wk[j][3], a1);
            }
            ov[j2] = __floats2bfloat162_rn(a0 / (1.f + __expf(-a0)),
                                           a1 / (1.f + __expf(-a1)));
        }
        *(uint4*)&g_ub[((size_t)(b * LL + l0 + s)) * DI + cbase] = out;
        #pragma unroll
        for (int j = 0; j < 8; j++) {
            xh[0][j] = xh[1][j];
            xh[1][j] = xh[2][j];
            xh[2][j] = xn[j];
        }
    }
}

// ---------------- scan phase A ----------------
__global__ void __launch_bounds__(128) scanA(const float* __restrict__ A_log) {
    extern __shared__ float smf[];
    float* s_r  = smf;
    float* s_bc = smf + 4096;
    __nv_bfloat16* s_w = (__nv_bfloat16*)(smf + 5120);
    float* s_part = smf + 7168;

    int b = blockIdx.z, chunk = blockIdx.y;
    int t = threadIdx.x;
    int d0 = blockIdx.x * 64;
    size_t base = (size_t)b * LL + (size_t)chunk * CH;

    {
        int chp = t & 63;
        int s0 = t >> 6;
        float sdt_part = 0.f;
        #pragma unroll 8
        for (int sI = s0; sI < CH; sI += 2) {
            size_t off = (base + sI) * DI + d0 + chp;
            float dtv = __bfloat162float(g_dtb[off]);
            float uv  = __bfloat162float(g_ub[off]);
            s_r[sI * 64 + chp] = __expf(-dtv);
            s_w[sI * 64 + chp] = __float2bfloat16(dtv * uv);
            sdt_part += dtv;
        }
        s_part[t] = sdt_part;
        #pragma unroll 4
        for (int i = t; i < CH * 16; i += 128) {
            int sI = i >> 4, j = i & 15;
            s_bc[sI * 16 + j] = g_proj[(base + sI) * NPROJ + DR + j];
        }
    }

    int half = t & 1;
    int ch = t >> 1;
    int d = d0 + ch;
    float Areg[8];
    bool fastp = true;
    #pragma unroll
    for (int n = 0; n < 8; n++) {
        Areg[n] = -__expf(A_log[d * DS + half * 8 + n]);
        float tgt = (float)(half * 8 + n + 1);
        fastp = fastp && (fabsf(Areg[n] + tgt) < 1e-5f * tgt);
    }
    float h[8];
    #pragma unroll
    for (int n = 0; n < 8; n++) h[n] = 0.f;
    __syncthreads();

    if (fastp) {
        #pragma unroll 4
        for (int sI = 0; sI < CH; sI++) {
            float r = s_r[sI * 64 + ch];
            float w = __bfloat162float(s_w[sI * 64 + ch]);
            const float* bcr = s_bc + sI * 16 + half * 8;
            float4 b0 = *(const float4*)bcr;
            float4 b1 = *(const float4*)(bcr + 4);
            float r2 = r * r, r4 = r2 * r2, r8 = r4 * r4;
            float p = half ? r8 * r : r;
            h[0] = fmaf(p, h[0], w * b0.x); p *= r;
            h[1] = fmaf(p, h[1], w * b0.y); p *= r;
            h[2] = fmaf(p, h[2], w * b0.z); p *= r;
            h[3] = fmaf(p, h[3], w * b0.w); p *= r;
            h[4] = fmaf(p, h[4], w * b1.x); p *= r;
            h[5] = fmaf(p, h[5], w * b1.y); p *= r;
            h[6] = fmaf(p, h[6], w * b1.z); p *= r;
            h[7] = fmaf(p, h[7], w * b1.w);
        }
    } else {
        for (int sI = 0; sI < CH; sI++) {
            float r = s_r[sI * 64 + ch];
            float dtv = -__logf(r);
            float w = __bfloat162float(s_w[sI * 64 + ch]);
            #pragma unroll
            for (int n = 0; n < 8; n++) {
                float dA = __expf(dtv * Areg[n]);
                h[n] = fmaf(dA, h[n], w * s_bc[sI * 16 + half * 8 + n]);
            }
        }
    }
    size_t sb = ((size_t)(b * NC + chunk) * DI + d) * DS + half * 8;
    *(float4*)&g_state[sb]     = make_float4(h[0], h[1], h[2], h[3]);
    *(float4*)&g_state[sb + 4] = make_float4(h[4], h[5], h[6], h[7]);
    if (!half) g_dtsum[(size_t)(b * NC + chunk) * DI + d] = s_part[ch] + s_part[ch + 64];
}

// ---------------- scan phase B ----------------
__global__ void __launch_bounds__(256) scanB(const float* __restrict__ A_log) {
    int tid = blockIdx.x * 256 + threadIdx.x;
    int d = tid & (DI - 1);
    int b = tid >> 11;
    float Areg[16];
    #pragma unroll
    for (int n = 0; n < 16; n++) Areg[n] = -__expf(A_log[d * DS + n]);
    float h[16];
    #pragma unroll
    for (int n = 0; n < 16; n++) h[n] = 0.f;
    for (int c = 0; c < NC; c++) {
        size_t sb = ((size_t)(b * NC + c) * DI + d) * DS;
        float4 e0 = *(float4*)&g_state[sb];
        float4 e1 = *(float4*)&g_state[sb + 4];
        float4 e2 = *(float4*)&g_state[sb + 8];
        float4 e3 = *(float4*)&g_state[sb + 12];
        float hend[16] = {e0.x,e0.y,e0.z,e0.w, e1.x,e1.y,e1.z,e1.w,
                          e2.x,e2.y,e2.z,e2.w, e3.x,e3.y,e3.z,e3.w};
        *(float4*)&g_state[sb]      = make_float4(h[0], h[1], h[2], h[3]);
        *(float4*)&g_state[sb + 4]  = make_float4(h[4], h[5], h[6], h[7]);
        *(float4*)&g_state[sb + 8]  = make_float4(h[8], h[9], h[10], h[11]);
        *(float4*)&g_state[sb + 12] = make_float4(h[12], h[13], h[14], h[15]);
        float S = g_dtsum[(size_t)(b * NC + c) * DI + d];
        #pragma unroll
        for (int n = 0; n < 16; n++) {
            float P = __expf(Areg[n] * S);
            h[n] = fmaf(P, h[n], hend[n]);
        }
    }
}

// ---------------- scan phase C ----------------
__global__ void __launch_bounds__(128) scanC(const float* __restrict__ A_log,
                                             const float* __restrict__ Dvec) {
    extern __shared__ float smf[];
    float* s_r  = smf;
    float* s_bc = smf + 4096;
    __nv_bfloat16* s_w = (__nv_bfloat16*)(smf + 6144);
    __nv_bfloat162* s_gu = (__nv_bfloat162*)(smf + 8192);

    int b = blockIdx.z, chunk = blockIdx.y;
    int t = threadIdx.x;
    int d0 = blockIdx.x * 64;
    size_t base = (size_t)b * LL + (size_t)chunk * CH;

    {
        int chp = t & 63;
        int s0 = t >> 6;
        float Dd = Dvec[d0 + chp];
        #pragma unroll 8
        for (int sI = s0; sI < CH; sI += 2) {
            size_t off = (base + sI) * DI + d0 + chp;
            float dtv = __bfloat162float(g_dtb[off]);
            float uv  = __bfloat162float(g_ub[off]);
            float zv  = __bfloat162float(g_xzb[(base + sI) * D2 + DI + d0 + chp]);
            float gate = zv / (1.f + __expf(-zv));
            s_r[sI * 64 + chp] = __expf(-dtv);
            s_w[sI * 64 + chp] = __float2bfloat16(dtv * uv);
            s_gu[sI * 64 + chp] = __floats2bfloat162_rn(gate, uv * Dd * gate);
        }
        #pragma unroll 4
        for (int i = t; i < CH * 32; i += 128) {
            int sI = i >> 5, j = i & 31;
            s_bc[sI * 32 + j] = g_proj[(base + sI) * NPROJ + DR + j];
        }
    }

    int half = t & 1, ch = t >> 1;
    int d = d0 + ch;
    float Areg[8];
    bool fastp = true;
    #pragma unroll
    for (int n = 0; n < 8; n++) {
        Areg[n] = -__expf(A_log[d * DS + half * 8 + n]);
        float tgt = (float)(half * 8 + n + 1);
        fastp = fastp && (fabsf(Areg[n] + tgt) < 1e-5f * tgt);
    }
    size_t sb = ((size_t)(b * NC + chunk) * DI + d) * DS + half * 8;
    float4 h0 = *(float4*)&g_state[sb];
    float4 h1 = *(float4*)&g_state[sb + 4];
    float h[8] = {h0.x, h0.y, h0.z, h0.w, h1.x, h1.y, h1.z, h1.w};
    __syncthreads();

    if (fastp) {
        #pragma unroll 2
        for (int sI = 0; sI < CH; sI++) {
            float r = s_r[sI * 64 + ch];
            float w = __bfloat162float(s_w[sI * 64 + ch]);
            const float* bcr = s_bc + sI * 32 + half * 8;
            float4 b0 = *(const float4*)bcr;
            float4 b1 = *(const float4*)(bcr + 4);
            float4 c0 = *(const float4*)(bcr + 16);
            float4 c1 = *(const float4*)(bcr + 20);
            float r2 = r * r, r4 = r2 * r2, r8 = r4 * r4;
            float p = half ? r8 * r : r;
            float y;
            h[0] = fmaf(p, h[0], w * b0.x); y = h[0] * c0.x;          p *= r;
            h[1] = fmaf(p, h[1], w * b0.y); y = fmaf(h[1], c0.y, y);  p *= r;
            h[2] = fmaf(p, h[2], w * b0.z); y = fmaf(h[2], c0.z, y);  p *= r;
            h[3] = fmaf(p, h[3], w * b0.w); y = fmaf(h[3], c0.w, y);  p *= r;
            h[4] = fmaf(p, h[4], w * b1.x); y = fmaf(h[4], c1.x, y);  p *= r;
            h[5] = fmaf(p, h[5], w * b1.y); y = fmaf(h[5], c1.y, y);  p *= r;
            h[6] = fmaf(p, h[6], w * b1.z); y = fmaf(h[6], c1.z, y);  p *= r;
            h[7] = fmaf(p, h[7], w * b1.w); y = fmaf(h[7], c1.w, y);
            y += __shfl_xor_sync(0xffffffffu, y, 1);
            if (!half) {
                float2 g = __bfloat1622float2(s_gu[sI * 64 + ch]);
                g_ygb[(base + sI) * DI + d] = __float2bfloat16(fmaf(y, g.x, g.y));
            }
        }
    } else {
        for (int sI = 0; sI < CH; sI++) {
            float r = s_r[sI * 64 + ch];
            float dtv = -__logf(r);
            float w = __bfloat162float(s_w[sI * 64 + ch]);
            float y = 0.f;
            #pragma unroll
            for (int n = 0; n < 8; n++) {
                float dA = __expf(dtv * Areg[n]);
                h[n] = fmaf(dA, h[n], w * s_bc[sI * 32 + half * 8 + n]);
                y = fmaf(h[n], s_bc[sI * 32 + 16 + half * 8 + n], y);
            }
            y += __shfl_xor_sync(0xffffffffu, y, 1);
            if (!half) {
                float2 g = __bfloat1622float2(s_gu[sI * 64 + ch]);
                g_ygb[(base + sI) * DI + d] = __float2bfloat16(fmaf(y, g.x, g.y));
            }
        }
    }
}

// ---------------- launch ----------------
extern "C" void kernel_launch(void* const* d_in, const int* in_sizes, int n_in,
                              void* d_out, int out_size) {
    const float* x       = (const float*)d_in[0];
    const float* ln_g    = (const float*)d_in[1];
    const float* ln_b    = (const float*)d_in[2];
    const float* W_in    = (const float*)d_in[3];
    const float* conv_w  = (const float*)d_in[4];
    const float* conv_b  = (const float*)d_in[5];
    const float* W_xproj = (const float*)d_in[6];
    const float* W_dt    = (const float*)d_in[7];
    const float* b_dt    = (const float*)d_in[8];
    const float* A_log   = (const float*)d_in[9];
    const float* Dvec    = (const float*)d_in[10];
    const float* W_out   = (const float*)d_in[11];
    float* out = (float*)d_out;

    float *p_projp;
    __nv_bfloat16 *p_hb, *p_xzb, *p_ub, *p_dtb, *p_ygb, *p_Winb, *p_Woutb, *p_Wxb, *p_Wdtb, *p_pdtb;
    cudaGetSymbolAddress((void**)&p_projp, g_projp);
    cudaGetSymbolAddress((void**)&p_hb,    g_hb);
    cudaGetSymbolAddress((void**)&p_xzb,   g_xzb);
    cudaGetSymbolAddress((void**)&p_ub,    g_ub);
    cudaGetSymbolAddress((void**)&p_dtb,   g_dtb);
    cudaGetSymbolAddress((void**)&p_ygb,   g_ygb);
    cudaGetSymbolAddress((void**)&p_Winb,  g_Winb);
    cudaGetSymbolAddress((void**)&p_Woutb, g_Woutb);
    cudaGetSymbolAddress((void**)&p_Wxb,   g_Wxb);
    cudaGetSymbolAddress((void**)&p_Wdtb,  g_Wdtb);
    cudaGetSymbolAddress((void**)&p_pdtb,  g_pdtb);

    const int smem_bytes = 4 * ASZ * 4;   // 73728 (2-stage GEMM, 2 blocks/SM)
    cudaFuncSetAttribute((gemm_bf16<0,true>),  cudaFuncAttributeMaxDynamicSharedMemorySize, smem_bytes);
    cudaFuncSetAttribute((gemm_bf16<1,false>), cudaFuncAttributeMaxDynamicSharedMemorySize, smem_bytes);
    cudaFuncSetAttribute((gemm_bf16<2,false>), cudaFuncAttributeMaxDynamicSharedMemorySize, smem_bytes);
    cudaFuncSetAttribute((gemm_bf16<3,false>), cudaFuncAttributeMaxDynamicSharedMemorySize, smem_bytes);
    cudaFuncSetAttribute(scanA, cudaFuncAttributeMaxDynamicSharedMemorySize, 29184);
    cudaFuncSetAttribute(scanC, cudaFuncAttributeMaxDynamicSharedMemorySize, 49152);

    // 1. LayerNorm -> bf16 h
    ln_kernel<<<MTOT, 256>>>(x, ln_g, ln_b);

    // 2. W_in -> bf16
    convert_win<<<(N4_WIN + 255) / 256, 256>>>(W_in);

    // 3. remaining weight conversions
    convert_rest<<<(N4_WOUT + N4_WX + N4_WDT + 255) / 256, 256>>>(W_out, W_xproj, W_dt);

    // 4. in_proj: M=8192 N=4096 K=1024
    {
        dim3 grid(D2 / 128, MTOT / 128);
        gemm_bf16<1,false><<<grid, 256, smem_bytes>>>(p_hb, DM, p_Winb, DM, nullptr,
                                                      p_xzb, MTOT, D2, D2, DM);
    }

    // 5. conv + SiLU -> u (sliding window)
    conv_kernel<<<((MTOT / CT) * 256) / 256, 256>>>(conv_w, conv_b);

    // 6. x_proj (split-K x4): N=96 (padded 128), K=2048
    {
        dim3 grid(1, MTOT / 128, KSPL);
        gemm_bf16<0,true><<<grid, 256, smem_bytes>>>(p_ub, DI, p_Wxb, DI, nullptr,
                                                     p_projp, MTOT, NPAD, NPROJ, DI / KSPL);
        reduce_proj<<<(MTOT * (NPROJ / 4) + 255) / 256, 256>>>();
    }

    // 7. dt (bias+softplus): M=8192 N=2048 K=64
    {
        dim3 grid(DI / 128, MTOT / 128);
        gemm_bf16<3,false><<<grid, 256, smem_bytes>>>(p_pdtb, DR, p_Wdtb, DR, b_dt,
                                                      p_dtb, MTOT, DI, DI, DR);
    }

    // 8. chunked selective scan (3-phase)
    {
        dim3 gridA(DI / 64, NC, BB);
        scanA<<<gridA, 128, 29184>>>(A_log);
        scanB<<<(BB * DI) / 256, 256>>>(A_log);
        scanC<<<gridA, 128, 49152>>>(A_log, Dvec);
    }

    // 9. out_proj (f32 + resid): M=8192 N=1024 K=2048
    {
        dim3 grid(DM / 128, MTOT / 128);
        gemm_bf16<2,false><<<grid, 256, smem_bytes>>>(p_ygb, DI, p_Woutb, DI, x,
                                                      out, MTOT, DM, DM, DI);
    }
}